// round 4
// baseline (speedup 1.0000x reference)
#include <cuda_runtime.h>
#include <math.h>

// Problem constants: N=20000, E=640000, S=128, V=16, E_DIM=32
#define MAXN 20000

__device__ float g_agg_s[MAXN * 128];
__device__ float g_agg_v[MAXN * 48];

typedef unsigned long long ull;

__device__ __forceinline__ float sigmoidf_(float x) {
    return 1.0f / (1.0f + __expf(-x));
}
// packed f32x2 helpers (Blackwell FFMA2 path)
__device__ __forceinline__ ull pk2(float x) {
    ull r; asm("mov.b64 %0, {%1, %1};" : "=l"(r) : "f"(x)); return r;
}
__device__ __forceinline__ void fma2_(ull& d, ull a, ull b) {
    asm("fma.rn.f32x2 %0, %1, %2, %0;" : "+l"(d) : "l"(a), "l"(b));
}
__device__ __forceinline__ float2 up2(ull p) {
    float2 r; asm("mov.b64 {%0, %1}, %2;" : "=f"(r.x), "=f"(r.y) : "l"(p)); return r;
}

// ---------------------------------------------------------------------------
__global__ void zero_kernel(int n) {
    int total = n * 176;
    for (int i = blockIdx.x * blockDim.x + threadIdx.x; i < total;
         i += gridDim.x * blockDim.x) {
        if (i < n * 128) g_agg_s[i] = 0.0f;
        else             g_agg_v[i - n * 128] = 0.0f;
    }
}

// ---------------------------------------------------------------------------
// Edge kernel: 64 edges/CTA, 256 threads, FFMA2 GEMMs.
// Shared layout (float offsets):
//   sxT  [336][68]  @ 0       (22848)   K-major X, stride 68
//   swt  [2][16][128] @ 22848 (4096)    double-buffered W tile
//   sv   [64][100]  @ 26944   (6400)    v inputs (33 x 3 per edge)
//   sg   [64][16]   @ 33344   (1024)
//   sWv  [33][16]   @ 34368   (528)
//   idx  128 ints   @ 34896   (128)
// aliases (inside sxT, dead after GEMM1/GEMM2 resp.):
//   stt  [64][132] @ 0     (8448)   silu(h), edge-major
//   sms  [64][132] @ 8448  (8448)   m_s
//   sWgT [16][128] @ 22848 (2048)   aliases swt (dead after GEMM2)
#define BE 64
#define ET 256
#define OFF_SWT 22848
#define OFF_SV  26944
#define OFF_SG  33344
#define OFF_SWV 34368
#define OFF_IDX 34896
#define EDGE_SMEM_BYTES (35024 * 4)

__global__ __launch_bounds__(256) void edge_kernel(
    const float* __restrict__ s, const float* __restrict__ v,
    const int* __restrict__ ei, const float* __restrict__ es,
    const float* __restrict__ ev,
    const float* __restrict__ W1, const float* __restrict__ b1,
    const float* __restrict__ W2, const float* __restrict__ b2,
    const float* __restrict__ Wv, const float* __restrict__ Wg,
    const float* __restrict__ bg, int E)
{
    extern __shared__ __align__(16) float sm[];
    float* sxT  = sm;
    float* swt  = sm + OFF_SWT;
    float* sv   = sm + OFF_SV;
    float* sg   = sm + OFF_SG;
    float* sWv  = sm + OFF_SWV;
    int*   ssrc = (int*)(sm + OFF_IDX);
    int*   sdst = ssrc + BE;
    float* stt  = sm;             // alias
    float* sms  = sm + 8448;      // alias
    float* sWgT = sm + OFF_SWT;   // alias

    const int tid = threadIdx.x;
    const int e0  = blockIdx.x * BE;
    const int nval = min(BE, E - e0);

    if (tid < BE) {
        int ee = e0 + min(tid, nval - 1);
        ssrc[tid] = ei[ee];
        sdst[tid] = ei[E + ee];
    }
    __syncthreads();

    // ---- gather scalar features into K-major X ----
    for (int idx = tid; idx < BE * 288; idx += ET) {
        int e = idx / 288;
        int k = idx - e * 288;
        int eg = e0 + (e < nval ? e : 0);
        float val;
        if (k < 128)      val = s[ssrc[e] * 128 + k];
        else if (k < 256) val = s[sdst[e] * 128 + (k - 128)];
        else              val = es[eg * 32 + (k - 256)];
        sxT[k * 68 + e] = val;
    }
    // ---- gather vector features ----
    for (int idx = tid; idx < BE * 99; idx += ET) {
        int e = idx / 99;
        int j = idx - e * 99;
        int eg = e0 + (e < nval ? e : 0);
        float val;
        if (j < 48)      val = v[ssrc[e] * 48 + j];
        else if (j < 96) val = v[sdst[e] * 48 + (j - 48)];
        else             val = ev[eg * 3 + (j - 96)];
        sv[e * 100 + j] = val;
    }
    // zero-pad K rows 322..335
    for (int idx = tid; idx < 14 * BE; idx += ET) {
        sxT[(322 + idx / BE) * 68 + (idx % BE)] = 0.0f;
    }
    __syncthreads();
    // ---- vector norms -> X rows 288..321 ----
    for (int idx = tid; idx < BE * 33; idx += ET) {
        int e = idx / 33;
        int j = idx - e * 33;
        float a = sv[e * 100 + j * 3 + 0];
        float b = sv[e * 100 + j * 3 + 1];
        float c = sv[e * 100 + j * 3 + 2];
        float nn = sqrtf(fmaxf(a * a + b * b + c * c, 1e-8f));
        sxT[(289 + j) * 68 + e] = nn;
        if (j == 32) sxT[288 * 68 + e] = nn;  // edge_len == |edge_v|
    }

    const int tx = tid & 15;   // 8 cols: 8*tx .. 8*tx+7
    const int ty = tid >> 4;   // 4 edges: 4*ty .. 4*ty+3

    ull acc[4][4];
#pragma unroll
    for (int i = 0; i < 4; ++i)
#pragma unroll
        for (int j = 0; j < 4; ++j) acc[i][j] = 0ull;

    // ---- GEMM1: K = 336 (21 tiles of 16), FFMA2 ----
    const float4* W14 = (const float4*)W1;
    {   // prefetch tile 0 (note: barrier below also covers gather/norm writes)
        float4* dst = (float4*)swt;
        for (int i = tid; i < 512; i += ET) {
            int k = i >> 5;
            dst[i] = (k < 322) ? W14[k * 32 + (i & 31)]
                               : make_float4(0.f, 0.f, 0.f, 0.f);
        }
    }
    __syncthreads();
    for (int kt = 0; kt < 21; ++kt) {
        if (kt + 1 < 21) {
            float4* dst = (float4*)(swt + ((kt + 1) & 1) * 2048);
            for (int i = tid; i < 512; i += ET) {
                int k = (kt + 1) * 16 + (i >> 5);
                dst[i] = (k < 322) ? W14[k * 32 + (i & 31)]
                                   : make_float4(0.f, 0.f, 0.f, 0.f);
            }
        }
        const float* wb = swt + (kt & 1) * 2048;
#pragma unroll 4
        for (int kk = 0; kk < 16; ++kk) {
            float4 xv = *(const float4*)&sxT[(kt * 16 + kk) * 68 + 4 * ty];
            const ulonglong2* wr = (const ulonglong2*)&wb[kk * 128 + 8 * tx];
            ulonglong2 wA = wr[0], wB = wr[1];
            ull xp[4] = {pk2(xv.x), pk2(xv.y), pk2(xv.z), pk2(xv.w)};
#pragma unroll
            for (int i = 0; i < 4; ++i) {
                fma2_(acc[i][0], xp[i], wA.x);
                fma2_(acc[i][1], xp[i], wA.y);
                fma2_(acc[i][2], xp[i], wB.x);
                fma2_(acc[i][3], xp[i], wB.y);
            }
        }
        __syncthreads();
    }

    // ---- epilogue 1: bias + silu -> stt (edge-major), then W2 tile0 ----
    {
        const float4* b14 = (const float4*)b1;
        float4 bA = b14[2 * tx], bB = b14[2 * tx + 1];
#pragma unroll
        for (int i = 0; i < 4; ++i) {
            float2 p0 = up2(acc[i][0]), p1 = up2(acc[i][1]);
            float2 p2 = up2(acc[i][2]), p3 = up2(acc[i][3]);
            float h[8] = {p0.x + bA.x, p0.y + bA.y, p1.x + bA.z, p1.y + bA.w,
                          p2.x + bB.x, p2.y + bB.y, p3.x + bB.z, p3.y + bB.w};
            float t[8];
#pragma unroll
            for (int j = 0; j < 8; ++j) t[j] = h[j] * sigmoidf_(h[j]);
            float* dst = &stt[(4 * ty + i) * 132 + 8 * tx];
            *(float4*)dst       = make_float4(t[0], t[1], t[2], t[3]);
            *(float4*)(dst + 4) = make_float4(t[4], t[5], t[6], t[7]);
        }
    }
    const float4* W24 = (const float4*)W2;
    {
        float4* dst = (float4*)swt;
        for (int i = tid; i < 512; i += ET)
            dst[i] = W24[(i >> 5) * 32 + (i & 31)];
    }
    __syncthreads();

    // ---- GEMM2: K = 128 (8 tiles of 16), FFMA2 ----
#pragma unroll
    for (int i = 0; i < 4; ++i)
#pragma unroll
        for (int j = 0; j < 4; ++j) acc[i][j] = 0ull;

    for (int kt = 0; kt < 8; ++kt) {
        if (kt + 1 < 8) {
            float4* dst = (float4*)(swt + ((kt + 1) & 1) * 2048);
            for (int i = tid; i < 512; i += ET) {
                int k = (kt + 1) * 16 + (i >> 5);
                dst[i] = W24[k * 32 + (i & 31)];
            }
        }
        const float* wb = swt + (kt & 1) * 2048;
#pragma unroll 4
        for (int kk = 0; kk < 16; ++kk) {
            int k = kt * 16 + kk;
            const ulonglong2* wr = (const ulonglong2*)&wb[kk * 128 + 8 * tx];
            ulonglong2 wA = wr[0], wB = wr[1];
            ull xp[4];
#pragma unroll
            for (int i = 0; i < 4; ++i)
                xp[i] = pk2(stt[(4 * ty + i) * 132 + k]);
#pragma unroll
            for (int i = 0; i < 4; ++i) {
                fma2_(acc[i][0], xp[i], wA.x);
                fma2_(acc[i][1], xp[i], wA.y);
                fma2_(acc[i][2], xp[i], wB.x);
                fma2_(acc[i][3], xp[i], wB.y);
            }
        }
        __syncthreads();
    }

    // ---- epilogue 2: bias -> sms, scatter-add m_s ----
    {
        const float4* b24 = (const float4*)b2;
        float4 bA = b24[2 * tx], bB = b24[2 * tx + 1];
#pragma unroll
        for (int i = 0; i < 4; ++i) {
            int e = 4 * ty + i;
            float2 p0 = up2(acc[i][0]), p1 = up2(acc[i][1]);
            float2 p2 = up2(acc[i][2]), p3 = up2(acc[i][3]);
            float m[8] = {p0.x + bA.x, p0.y + bA.y, p1.x + bA.z, p1.y + bA.w,
                          p2.x + bB.x, p2.y + bB.y, p3.x + bB.z, p3.y + bB.w};
            float* dst = &sms[e * 132 + 8 * tx];
            *(float4*)dst       = make_float4(m[0], m[1], m[2], m[3]);
            *(float4*)(dst + 4) = make_float4(m[4], m[5], m[6], m[7]);
            if (e < nval) {
                float* ga = &g_agg_s[sdst[e] * 128 + 8 * tx];
#pragma unroll
                for (int j = 0; j < 8; ++j) atomicAdd(ga + j, m[j]);
            }
        }
    }
    // stage Wg^T and Wv into smem (swt dead now)
    for (int i = tid; i < 2048; i += ET) {
        int w = i >> 7, c = i & 127;
        sWgT[i] = Wg[c * 16 + w];
    }
    for (int i = tid; i < 528; i += ET) sWv[i] = Wv[i];
    __syncthreads();

    // ---- gates: sigmoid(ms @ Wg + bg), FFMA2 ----
    for (int q = tid; q < BE * 16; q += ET) {
        int e = q >> 4, w = q & 15;
        ull g2 = 0ull;
        const ull* msp = (const ull*)&sms[e * 132];
        const ull* wgp = (const ull*)&sWgT[w * 128];
#pragma unroll 8
        for (int c = 0; c < 64; ++c) fma2_(g2, msp[c], wgp[c]);
        float2 gf = up2(g2);
        sg[e * 16 + w] = sigmoidf_(gf.x + gf.y + bg[w]);
    }
    __syncthreads();

    // ---- v projection * gate, scatter-add ----
    for (int q = tid; q < BE * 48; q += ET) {
        int e  = q / 48;
        int r  = q - e * 48;
        int w  = r / 3;
        int cc = r - w * 3;
        float a = 0.0f;
#pragma unroll
        for (int j = 0; j < 33; ++j)
            a = fmaf(sv[e * 100 + j * 3 + cc], sWv[j * 16 + w], a);
        a *= sg[e * 16 + w];
        if (e < nval) atomicAdd(&g_agg_v[sdst[e] * 48 + r], a);
    }
}

// ---------------------------------------------------------------------------
// Node update kernel (unchanged from working r1 kernel)
// ---------------------------------------------------------------------------
__global__ __launch_bounds__(128) void node_kernel(
    const float* __restrict__ s, const float* __restrict__ v,
    const float* __restrict__ W1, const float* __restrict__ b1,
    const float* __restrict__ W2, const float* __restrict__ b2,
    const float* __restrict__ Wv, const float* __restrict__ Wg,
    const float* __restrict__ bg, const float* __restrict__ lng,
    const float* __restrict__ lnb,
    float* __restrict__ out_s, float* __restrict__ out_v, int n)
{
    __shared__ float xu[8][292];
    __shared__ float vin[8][96];
    __shared__ float tt[8][128];
    __shared__ float dsm[8][132];
    __shared__ float gate[8][16];
    __shared__ float rsum[8][4], rsq[8][4];

    const int tid = threadIdx.x;
    const int n0 = blockIdx.x * 8;

    for (int idx = tid; idx < 8 * 256; idx += 128) {
        int i = idx >> 8, k = idx & 255;
        int nd = min(n0 + i, n - 1);
        xu[i][k] = (k < 128) ? s[nd * 128 + k] : g_agg_s[nd * 128 + (k - 128)];
    }
    for (int idx = tid; idx < 8 * 96; idx += 128) {
        int i = idx / 96, k = idx - i * 96;
        int nd = min(n0 + i, n - 1);
        vin[i][k] = (k < 48) ? v[nd * 48 + k] : g_agg_v[nd * 48 + (k - 48)];
    }
    __syncthreads();
    for (int idx = tid; idx < 8 * 32; idx += 128) {
        int i = idx >> 5, j = idx & 31;
        float a = vin[i][j * 3], b = vin[i][j * 3 + 1], c = vin[i][j * 3 + 2];
        xu[i][256 + j] = sqrtf(fmaxf(a * a + b * b + c * c, 1e-8f));
    }
    __syncthreads();

    const int c = tid;
    float acc[8];
    {
        float bb = b1[c];
#pragma unroll
        for (int i = 0; i < 8; ++i) acc[i] = bb;
    }
    for (int k = 0; k < 288; ++k) {
        float w = W1[k * 128 + c];
#pragma unroll
        for (int i = 0; i < 8; ++i) acc[i] = fmaf(xu[i][k], w, acc[i]);
    }
#pragma unroll
    for (int i = 0; i < 8; ++i) {
        float h = acc[i];
        tt[i][c] = h * sigmoidf_(h);
    }
    __syncthreads();

    float acc2[8];
    {
        float bb = b2[c];
#pragma unroll
        for (int i = 0; i < 8; ++i) acc2[i] = bb;
    }
    for (int k = 0; k < 128; ++k) {
        float w = W2[k * 128 + c];
#pragma unroll
        for (int i = 0; i < 8; ++i) acc2[i] = fmaf(tt[i][k], w, acc2[i]);
    }
#pragma unroll
    for (int i = 0; i < 8; ++i) dsm[i][c] = acc2[i];
    __syncthreads();

    {
        int i = tid >> 4, w = tid & 15;
        float g = bg[w];
        for (int cc = 0; cc < 128; ++cc)
            g = fmaf(dsm[i][cc], Wg[cc * 16 + w], g);
        gate[i][w] = sigmoidf_(g);
    }

    float val[8];
#pragma unroll
    for (int i = 0; i < 8; ++i) {
        int nd = min(n0 + i, n - 1);
        val[i] = s[nd * 128 + c] + acc2[i];
    }
    const int lane = tid & 31, wq = tid >> 5;
    float psum[8], psq[8];
#pragma unroll
    for (int i = 0; i < 8; ++i) { psum[i] = val[i]; psq[i] = val[i] * val[i]; }
#pragma unroll
    for (int off = 16; off > 0; off >>= 1) {
#pragma unroll
        for (int i = 0; i < 8; ++i) {
            psum[i] += __shfl_xor_sync(0xffffffffu, psum[i], off);
            psq[i]  += __shfl_xor_sync(0xffffffffu, psq[i],  off);
        }
    }
    if (lane == 0) {
#pragma unroll
        for (int i = 0; i < 8; ++i) { rsum[i][wq] = psum[i]; rsq[i][wq] = psq[i]; }
    }
    __syncthreads();

#pragma unroll
    for (int i = 0; i < 8; ++i) {
        if (n0 + i >= n) continue;
        float sum = rsum[i][0] + rsum[i][1] + rsum[i][2] + rsum[i][3];
        float sq  = rsq[i][0] + rsq[i][1] + rsq[i][2] + rsq[i][3];
        float mu  = sum * (1.0f / 128.0f);
        float var = sq * (1.0f / 128.0f) - mu * mu;
        float o = (val[i] - mu) * rsqrtf(var + 1e-5f) * lng[c] + lnb[c];
        out_s[(n0 + i) * 128 + c] = o;
    }

    for (int q = tid; q < 8 * 48; q += 128) {
        int i = q / 48, r = q - i * 48;
        if (n0 + i >= n) continue;
        int w = r / 3, cc = r - w * 3;
        float a = 0.0f;
#pragma unroll
        for (int j = 0; j < 32; ++j)
            a = fmaf(vin[i][j * 3 + cc], Wv[j * 16 + w], a);
        a *= gate[i][w];
        out_v[(n0 + i) * 48 + r] = v[(n0 + i) * 48 + r] + a;
    }
}

// ---------------------------------------------------------------------------
extern "C" void kernel_launch(void* const* d_in, const int* in_sizes, int n_in,
                              void* d_out, int out_size)
{
    const float* s   = (const float*)d_in[0];
    const float* v   = (const float*)d_in[1];
    const int*   ei  = (const int*)  d_in[2];
    const float* es  = (const float*)d_in[3];
    const float* ev  = (const float*)d_in[4];
    const float* mW1 = (const float*)d_in[5];
    const float* mb1 = (const float*)d_in[6];
    const float* mW2 = (const float*)d_in[7];
    const float* mb2 = (const float*)d_in[8];
    const float* mWv = (const float*)d_in[9];
    const float* mWg = (const float*)d_in[10];
    const float* mbg = (const float*)d_in[11];
    const float* uW1 = (const float*)d_in[12];
    const float* ub1 = (const float*)d_in[13];
    const float* uW2 = (const float*)d_in[14];
    const float* ub2 = (const float*)d_in[15];
    const float* uWv = (const float*)d_in[16];
    const float* uWg = (const float*)d_in[17];
    const float* ubg = (const float*)d_in[18];
    const float* lng = (const float*)d_in[19];
    const float* lnb = (const float*)d_in[20];

    const int n = in_sizes[0] / 128;
    const int E = in_sizes[2] / 2;

    float* out_s = (float*)d_out;
    float* out_v = out_s + (size_t)n * 128;

    cudaFuncSetAttribute(edge_kernel,
                         cudaFuncAttributeMaxDynamicSharedMemorySize,
                         EDGE_SMEM_BYTES);

    zero_kernel<<<(n * 176 + 255) / 256, 256>>>(n);

    edge_kernel<<<(E + BE - 1) / BE, ET, EDGE_SMEM_BYTES>>>(
        s, v, ei, es, ev, mW1, mb1, mW2, mb2, mWv, mWg, mbg, E);

    node_kernel<<<(n + 7) / 8, 128>>>(
        s, v, uW1, ub1, uW2, ub2, uWv, uWg, ubg, lng, lnb,
        out_s, out_v, n);
}

// round 6
// speedup vs baseline: 2.0819x; 2.0819x over previous
#include <cuda_runtime.h>
#include <cuda_bf16.h>
#include <math.h>
#include <stdint.h>

// Problem constants: N=20000, E=640000, S=128, V=16, E_DIM=32
#define MAXN 20000

__device__ float g_agg_s[MAXN * 128];
__device__ float g_agg_v[MAXN * 48];

__device__ __forceinline__ float sigmoidf_(float x) {
    return 1.0f / (1.0f + __expf(-x));
}
__device__ __forceinline__ uint32_t smem_to_u32(const void* p) {
    uint32_t a;
    asm("{ .reg .u64 t; cvta.to.shared.u64 t, %1; cvt.u32.u64 %0, t; }"
        : "=r"(a) : "l"(p));
    return a;
}
__device__ __forceinline__ void ldsm4(uint32_t addr, uint32_t* r) {
    asm volatile("ldmatrix.sync.aligned.m8n8.x4.shared.b16 {%0,%1,%2,%3}, [%4];"
        : "=r"(r[0]), "=r"(r[1]), "=r"(r[2]), "=r"(r[3]) : "r"(addr));
}
__device__ __forceinline__ void ldsm4t(uint32_t addr, uint32_t* r) {
    asm volatile("ldmatrix.sync.aligned.m8n8.x4.trans.shared.b16 {%0,%1,%2,%3}, [%4];"
        : "=r"(r[0]), "=r"(r[1]), "=r"(r[2]), "=r"(r[3]) : "r"(addr));
}
__device__ __forceinline__ void mma_bf16(float* c, const uint32_t* a, const uint32_t* b) {
    asm volatile(
        "mma.sync.aligned.m16n8k16.row.col.f32.bf16.bf16.f32 "
        "{%0,%1,%2,%3}, {%4,%5,%6,%7}, {%8,%9}, {%0,%1,%2,%3};"
        : "+f"(c[0]), "+f"(c[1]), "+f"(c[2]), "+f"(c[3])
        : "r"(a[0]), "r"(a[1]), "r"(a[2]), "r"(a[3]), "r"(b[0]), "r"(b[1]));
}
__device__ __forceinline__ uint32_t pack_bf2(float x0, float x1) {
    __nv_bfloat162 t;
    t.x = __float2bfloat16(x0);
    t.y = __float2bfloat16(x1);
    return *(uint32_t*)&t;
}
__device__ __forceinline__ void red4(float* p, float a, float b, float c, float d) {
    asm volatile("red.global.add.v4.f32 [%0], {%1, %2, %3, %4};"
        :: "l"(p), "f"(a), "f"(b), "f"(c), "f"(d) : "memory");
}

// ---------------------------------------------------------------------------
__global__ void zero_kernel(int n) {
    int total = n * 176;
    for (int i = blockIdx.x * blockDim.x + threadIdx.x; i < total;
         i += gridDim.x * blockDim.x) {
        if (i < n * 128) g_agg_s[i] = 0.0f;
        else             g_agg_v[i - n * 128] = 0.0f;
    }
}

// ===========================================================================
// Edge kernel: 128 edges/CTA, 256 threads, mma.sync bf16 (3-term hi/lo split).
// smem byte map (total 110080):
//   [0, 69632)      Thi [128][136]bf16 @0, Tlo @34816
//                   later: sms f32 [128][132] @0 ; later: svin f32 [128][100] @0
//   [69632,100352)  snorm f32[128][36] @69632 ; Xhi bf16[128][24] @88064 ; Xlo @94208
//                   later: WgT f32[16][128] @69632 ; Wv @77824 ; sg f32[128][16] @80000
//   [100352,109056) Whi bf16[16][136] @100352 ; Wlo @104704
//   [109056,110080) ssrc int[128] @109056 ; sdst @109568
// ===========================================================================
#define OB_T     0
#define OB_TLO   34816
#define OB_NORM  69632
#define OB_XHI   88064
#define OB_XLO   94208
#define OB_WGT   69632
#define OB_WV    77824
#define OB_SG    80000
#define OB_WHI   100352
#define OB_WLO   104704
#define OB_SRC   109056
#define OB_DST   109568
#define EDGE_SMEM_BYTES 110080

__device__ __forceinline__ float fetch_x(int k, int e, int eg,
    const float* __restrict__ s, const float* __restrict__ es,
    const int* ssrc, const int* sdst, const float* snorm)
{
    if (k < 128)  return s[ssrc[e] * 128 + k];
    if (k < 256)  return s[sdst[e] * 128 + (k - 128)];
    if (k < 288)  return es[eg * 32 + (k - 256)];
    if (k == 288) return snorm[e * 36 + 32];      // edge_len = |edge_v|
    if (k < 322)  return snorm[e * 36 + (k - 289)];
    return 0.0f;                                  // K padding 322..335
}

__global__ __launch_bounds__(256, 2) void edge_kernel(
    const float* __restrict__ s, const float* __restrict__ v,
    const int* __restrict__ ei, const float* __restrict__ es,
    const float* __restrict__ ev,
    const float* __restrict__ W1, const float* __restrict__ b1,
    const float* __restrict__ W2, const float* __restrict__ b2,
    const float* __restrict__ Wv, const float* __restrict__ Wg,
    const float* __restrict__ bg, int E)
{
    extern __shared__ __align__(16) char smraw[];
    float* smf = (float*)smraw;
    const uint32_t smb = smem_to_u32(smraw);

    const int tid = threadIdx.x;
    const int lane = tid & 31;
    const int wid = tid >> 5;
    const int e0 = blockIdx.x * 128;
    const int nval = min(128, E - e0);

    int* ssrc = (int*)(smraw + OB_SRC);
    int* sdst = (int*)(smraw + OB_DST);
    float* snorm = (float*)(smraw + OB_NORM);

    // ---- phase 1: indices + vector norms ----
    if (tid < 128) {
        int ee = e0 + min(tid, nval - 1);
        ssrc[tid] = ei[ee];
        sdst[tid] = ei[E + ee];
    }
    __syncthreads();
    for (int q = tid; q < 128 * 33; q += 256) {
        int e = q / 33, j = q - e * 33;
        int eg = e0 + min(e, nval - 1);
        float a, b, c;
        if (j < 16) {
            const float* p = v + (size_t)ssrc[e] * 48 + j * 3;
            a = p[0]; b = p[1]; c = p[2];
        } else if (j < 32) {
            const float* p = v + (size_t)sdst[e] * 48 + (j - 16) * 3;
            a = p[0]; b = p[1]; c = p[2];
        } else {
            const float* p = ev + (size_t)eg * 3;
            a = p[0]; b = p[1]; c = p[2];
        }
        snorm[e * 36 + j] = sqrtf(fmaxf(a * a + b * b + c * c, 1e-8f));
    }
    __syncthreads();

    // warp tiling: 4 warps along M (edges), 2 along N
    const int mw = (wid & 3) * 32;
    const int nw = (wid >> 2) * 64;
    const int arow = lane & 15;      // ldmatrix row
    const int acol = lane >> 4;      // 8-col selector

    float acc[2][8][4];
#pragma unroll
    for (int mt = 0; mt < 2; ++mt)
#pragma unroll
        for (int nt = 0; nt < 8; ++nt)
#pragma unroll
            for (int r = 0; r < 4; ++r) acc[mt][nt][r] = 0.0f;

    // ================= GEMM1: h = X @ W1  (M=128, N=128, K=336) =============
    for (int kt = 0; kt < 21; ++kt) {
        // build X k-tile [128][16] hi/lo
        for (int q = tid; q < 2048; q += 256) {
            int e = q >> 4, kk = q & 15;
            int k = kt * 16 + kk;
            int eg = e0 + min(e, nval - 1);
            float val = fetch_x(k, e, eg, s, es, ssrc, sdst, snorm);
            __nv_bfloat16 h = __float2bfloat16(val);
            float rl = val - __bfloat162float(h);
            *(__nv_bfloat16*)(smraw + OB_XHI + e * 48 + kk * 2) = h;
            *(__nv_bfloat16*)(smraw + OB_XLO + e * 48 + kk * 2) = __float2bfloat16(rl);
        }
        // build W1 k-tile [16][128] hi/lo (stride 136)
        for (int q = tid; q < 2048; q += 256) {
            int kk = q >> 7, n = q & 127;
            int k = kt * 16 + kk;
            float val = (k < 322) ? W1[k * 128 + n] : 0.0f;
            __nv_bfloat16 h = __float2bfloat16(val);
            float rl = val - __bfloat162float(h);
            *(__nv_bfloat16*)(smraw + OB_WHI + kk * 272 + n * 2) = h;
            *(__nv_bfloat16*)(smraw + OB_WLO + kk * 272 + n * 2) = __float2bfloat16(rl);
        }
        __syncthreads();
        uint32_t ah[2][4], al[2][4];
#pragma unroll
        for (int mt = 0; mt < 2; ++mt) {
            uint32_t aaddr = smb + OB_XHI + (mw + 16 * mt + arow) * 48 + acol * 16;
            ldsm4(aaddr, ah[mt]);
            ldsm4(aaddr + (OB_XLO - OB_XHI), al[mt]);
        }
#pragma unroll
        for (int nb = 0; nb < 4; ++nb) {
            uint32_t bh[4], bl[4];
            uint32_t baddr = smb + OB_WHI + arow * 272 + (nw + nb * 16 + acol * 8) * 2;
            ldsm4t(baddr, bh);
            ldsm4t(baddr + (OB_WLO - OB_WHI), bl);
#pragma unroll
            for (int mt = 0; mt < 2; ++mt) {
                mma_bf16(acc[mt][2 * nb],     ah[mt], bh);
                mma_bf16(acc[mt][2 * nb + 1], ah[mt], bh + 2);
                mma_bf16(acc[mt][2 * nb],     al[mt], bh);
                mma_bf16(acc[mt][2 * nb + 1], al[mt], bh + 2);
                mma_bf16(acc[mt][2 * nb],     ah[mt], bl);
                mma_bf16(acc[mt][2 * nb + 1], ah[mt], bl + 2);
            }
        }
        __syncthreads();
    }

    // ---- epilogue 1: +b1, silu, bf16 split -> T ----
#pragma unroll
    for (int mt = 0; mt < 2; ++mt) {
        int r0 = mw + 16 * mt + (lane >> 2);
#pragma unroll
        for (int nt = 0; nt < 8; ++nt) {
            int n = nw + nt * 8 + (lane & 3) * 2;
            float2 bb = *(const float2*)&b1[n];
            float h0 = acc[mt][nt][0] + bb.x, h1 = acc[mt][nt][1] + bb.y;
            float h2 = acc[mt][nt][2] + bb.x, h3 = acc[mt][nt][3] + bb.y;
            float t0 = h0 * sigmoidf_(h0), t1 = h1 * sigmoidf_(h1);
            float t2 = h2 * sigmoidf_(h2), t3 = h3 * sigmoidf_(h3);
            uint32_t p0h = pack_bf2(t0, t1);
            __nv_bfloat162 u0 = *(__nv_bfloat162*)&p0h;
            uint32_t p0l = pack_bf2(t0 - __bfloat162float(u0.x), t1 - __bfloat162float(u0.y));
            uint32_t p1h = pack_bf2(t2, t3);
            __nv_bfloat162 u1 = *(__nv_bfloat162*)&p1h;
            uint32_t p1l = pack_bf2(t2 - __bfloat162float(u1.x), t3 - __bfloat162float(u1.y));
            *(uint32_t*)(smraw + OB_T   + r0 * 272 + n * 2) = p0h;
            *(uint32_t*)(smraw + OB_TLO + r0 * 272 + n * 2) = p0l;
            *(uint32_t*)(smraw + OB_T   + (r0 + 8) * 272 + n * 2) = p1h;
            *(uint32_t*)(smraw + OB_TLO + (r0 + 8) * 272 + n * 2) = p1l;
        }
    }
    __syncthreads();

    // stage Wg^T and Wv (norm/X region is dead now)
    for (int q = tid; q < 2048; q += 256) {
        int w = q >> 7, c = q & 127;
        smf[OB_WGT / 4 + q] = Wg[c * 16 + w];
    }
    for (int q = tid; q < 528; q += 256) smf[OB_WV / 4 + q] = Wv[q];

    // ================= GEMM2: m_s = silu(h) @ W2  (K=128) ====================
#pragma unroll
    for (int mt = 0; mt < 2; ++mt)
#pragma unroll
        for (int nt = 0; nt < 8; ++nt)
#pragma unroll
            for (int r = 0; r < 4; ++r) acc[mt][nt][r] = 0.0f;

    for (int kt = 0; kt < 8; ++kt) {
        for (int q = tid; q < 2048; q += 256) {
            int kk = q >> 7, n = q & 127;
            int k = kt * 16 + kk;
            float val = W2[k * 128 + n];
            __nv_bfloat16 h = __float2bfloat16(val);
            float rl = val - __bfloat162float(h);
            *(__nv_bfloat16*)(smraw + OB_WHI + kk * 272 + n * 2) = h;
            *(__nv_bfloat16*)(smraw + OB_WLO + kk * 272 + n * 2) = __float2bfloat16(rl);
        }
        __syncthreads();
        uint32_t ah[2][4], al[2][4];
#pragma unroll
        for (int mt = 0; mt < 2; ++mt) {
            uint32_t aaddr = smb + OB_T + (mw + 16 * mt + arow) * 272
                           + (kt * 16 + acol * 8) * 2;
            ldsm4(aaddr, ah[mt]);
            ldsm4(aaddr + (OB_TLO - OB_T), al[mt]);
        }
#pragma unroll
        for (int nb = 0; nb < 4; ++nb) {
            uint32_t bh[4], bl[4];
            uint32_t baddr = smb + OB_WHI + arow * 272 + (nw + nb * 16 + acol * 8) * 2;
            ldsm4t(baddr, bh);
            ldsm4t(baddr + (OB_WLO - OB_WHI), bl);
#pragma unroll
            for (int mt = 0; mt < 2; ++mt) {
                mma_bf16(acc[mt][2 * nb],     ah[mt], bh);
                mma_bf16(acc[mt][2 * nb + 1], ah[mt], bh + 2);
                mma_bf16(acc[mt][2 * nb],     al[mt], bh);
                mma_bf16(acc[mt][2 * nb + 1], al[mt], bh + 2);
                mma_bf16(acc[mt][2 * nb],     ah[mt], bl);
                mma_bf16(acc[mt][2 * nb + 1], ah[mt], bl + 2);
            }
        }
        __syncthreads();
    }

    // ---- epilogue 2: +b2 -> sms (aliases T; all T reads completed) ----
    float* sms = smf;  // [128][132]
#pragma unroll
    for (int mt = 0; mt < 2; ++mt) {
        int r0 = mw + 16 * mt + (lane >> 2);
#pragma unroll
        for (int nt = 0; nt < 8; ++nt) {
            int n = nw + nt * 8 + (lane & 3) * 2;
            float2 bb = *(const float2*)&b2[n];
            sms[r0 * 132 + n]       = acc[mt][nt][0] + bb.x;
            sms[r0 * 132 + n + 1]   = acc[mt][nt][1] + bb.y;
            sms[(r0 + 8) * 132 + n]     = acc[mt][nt][2] + bb.x;
            sms[(r0 + 8) * 132 + n + 1] = acc[mt][nt][3] + bb.y;
        }
    }
    __syncthreads();

    // ---- gates: sigmoid(ms @ Wg + bg) ----
    float* sg = smf + OB_SG / 4;
    for (int q = tid; q < 2048; q += 256) {
        int e = q >> 4, w = q & 15;
        float g = 0.0f;
        const float4* ms4 = (const float4*)(sms + e * 132);
        const float4* wg4 = (const float4*)(smf + OB_WGT / 4 + w * 128);
#pragma unroll 8
        for (int c4 = 0; c4 < 32; ++c4) {
            float4 a = ms4[c4], b = wg4[c4];
            g += a.x * b.x + a.y * b.y + a.z * b.z + a.w * b.w;
        }
        sg[e * 16 + w] = sigmoidf_(g + bg[w]);
    }
    __syncthreads();

    // ---- scatter-add m_s ----
    for (int q = tid; q < 4096; q += 256) {
        int e = q >> 5, cq = q & 31;
        if (e < nval) {
            const float* p = sms + e * 132 + cq * 4;
            red4(&g_agg_s[(size_t)sdst[e] * 128 + cq * 4], p[0], p[1], p[2], p[3]);
        }
    }
    __syncthreads();

    // ---- gather vin (aliases sms region, now dead) ----
    float* svin = smf;  // [128][100]
    for (int q = tid; q < 128 * 99; q += 256) {
        int e = q / 99, j = q - e * 99;
        int eg = e0 + min(e, nval - 1);
        float val;
        if (j < 48)      val = v[(size_t)ssrc[e] * 48 + j];
        else if (j < 96) val = v[(size_t)sdst[e] * 48 + (j - 48)];
        else             val = ev[(size_t)eg * 3 + (j - 96)];
        svin[e * 100 + j] = val;
    }
    __syncthreads();

    // ---- v projection * gate, scatter-add ----
    for (int q = tid; q < 1536; q += 256) {
        int e = q / 12, rq = q - e * 12;
        if (e >= nval) continue;
        float out[4];
#pragma unroll
        for (int u = 0; u < 4; ++u) {
            int r = rq * 4 + u, w = r / 3, c3 = r - w * 3;
            float a = 0.0f;
#pragma unroll
            for (int j = 0; j < 33; ++j)
                a = fmaf(svin[e * 100 + j * 3 + c3], smf[OB_WV / 4 + j * 16 + w], a);
            out[u] = a * sg[e * 16 + w];
        }
        red4(&g_agg_v[(size_t)sdst[e] * 48 + rq * 4], out[0], out[1], out[2], out[3]);
    }
}

// ---------------------------------------------------------------------------
// Node update kernel (r1, verified correct)
// ---------------------------------------------------------------------------
__global__ __launch_bounds__(128) void node_kernel(
    const float* __restrict__ s, const float* __restrict__ v,
    const float* __restrict__ W1, const float* __restrict__ b1,
    const float* __restrict__ W2, const float* __restrict__ b2,
    const float* __restrict__ Wv, const float* __restrict__ Wg,
    const float* __restrict__ bg, const float* __restrict__ lng,
    const float* __restrict__ lnb,
    float* __restrict__ out_s, float* __restrict__ out_v, int n)
{
    __shared__ float xu[8][292];
    __shared__ float vin[8][96];
    __shared__ float tt[8][128];
    __shared__ float dsm[8][132];
    __shared__ float gate[8][16];
    __shared__ float rsum[8][4], rsq[8][4];

    const int tid = threadIdx.x;
    const int n0 = blockIdx.x * 8;

    for (int idx = tid; idx < 8 * 256; idx += 128) {
        int i = idx >> 8, k = idx & 255;
        int nd = min(n0 + i, n - 1);
        xu[i][k] = (k < 128) ? s[nd * 128 + k] : g_agg_s[nd * 128 + (k - 128)];
    }
    for (int idx = tid; idx < 8 * 96; idx += 128) {
        int i = idx / 96, k = idx - i * 96;
        int nd = min(n0 + i, n - 1);
        vin[i][k] = (k < 48) ? v[nd * 48 + k] : g_agg_v[nd * 48 + (k - 48)];
    }
    __syncthreads();
    for (int idx = tid; idx < 8 * 32; idx += 128) {
        int i = idx >> 5, j = idx & 31;
        float a = vin[i][j * 3], b = vin[i][j * 3 + 1], c = vin[i][j * 3 + 2];
        xu[i][256 + j] = sqrtf(fmaxf(a * a + b * b + c * c, 1e-8f));
    }
    __syncthreads();

    const int c = tid;
    float acc[8];
    {
        float bb = b1[c];
#pragma unroll
        for (int i = 0; i < 8; ++i) acc[i] = bb;
    }
    for (int k = 0; k < 288; ++k) {
        float w = W1[k * 128 + c];
#pragma unroll
        for (int i = 0; i < 8; ++i) acc[i] = fmaf(xu[i][k], w, acc[i]);
    }
#pragma unroll
    for (int i = 0; i < 8; ++i) {
        float h = acc[i];
        tt[i][c] = h * sigmoidf_(h);
    }
    __syncthreads();

    float acc2[8];
    {
        float bb = b2[c];
#pragma unroll
        for (int i = 0; i < 8; ++i) acc2[i] = bb;
    }
    for (int k = 0; k < 128; ++k) {
        float w = W2[k * 128 + c];
#pragma unroll
        for (int i = 0; i < 8; ++i) acc2[i] = fmaf(tt[i][k], w, acc2[i]);
    }
#pragma unroll
    for (int i = 0; i < 8; ++i) dsm[i][c] = acc2[i];
    __syncthreads();

    {
        int i = tid >> 4, w = tid & 15;
        float g = bg[w];
        for (int cc = 0; cc < 128; ++cc)
            g = fmaf(dsm[i][cc], Wg[cc * 16 + w], g);
        gate[i][w] = sigmoidf_(g);
    }

    float val[8];
#pragma unroll
    for (int i = 0; i < 8; ++i) {
        int nd = min(n0 + i, n - 1);
        val[i] = s[nd * 128 + c] + acc2[i];
    }
    const int lane = tid & 31, wq = tid >> 5;
    float psum[8], psq[8];
#pragma unroll
    for (int i = 0; i < 8; ++i) { psum[i] = val[i]; psq[i] = val[i] * val[i]; }
#pragma unroll
    for (int off = 16; off > 0; off >>= 1) {
#pragma unroll
        for (int i = 0; i < 8; ++i) {
            psum[i] += __shfl_xor_sync(0xffffffffu, psum[i], off);
            psq[i]  += __shfl_xor_sync(0xffffffffu, psq[i],  off);
        }
    }
    if (lane == 0) {
#pragma unroll
        for (int i = 0; i < 8; ++i) { rsum[i][wq] = psum[i]; rsq[i][wq] = psq[i]; }
    }
    __syncthreads();

#pragma unroll
    for (int i = 0; i < 8; ++i) {
        if (n0 + i >= n) continue;
        float sum = rsum[i][0] + rsum[i][1] + rsum[i][2] + rsum[i][3];
        float sq  = rsq[i][0] + rsq[i][1] + rsq[i][2] + rsq[i][3];
        float mu  = sum * (1.0f / 128.0f);
        float var = sq * (1.0f / 128.0f) - mu * mu;
        float o = (val[i] - mu) * rsqrtf(var + 1e-5f) * lng[c] + lnb[c];
        out_s[(n0 + i) * 128 + c] = o;
    }

    for (int q = tid; q < 8 * 48; q += 128) {
        int i = q / 48, r = q - i * 48;
        if (n0 + i >= n) continue;
        int w = r / 3, cc = r - w * 3;
        float a = 0.0f;
#pragma unroll
        for (int j = 0; j < 32; ++j)
            a = fmaf(vin[i][j * 3 + cc], Wv[j * 16 + w], a);
        a *= gate[i][w];
        out_v[(n0 + i) * 48 + r] = v[(n0 + i) * 48 + r] + a;
    }
}

// ---------------------------------------------------------------------------
extern "C" void kernel_launch(void* const* d_in, const int* in_sizes, int n_in,
                              void* d_out, int out_size)
{
    const float* s   = (const float*)d_in[0];
    const float* v   = (const float*)d_in[1];
    const int*   ei  = (const int*)  d_in[2];
    const float* es  = (const float*)d_in[3];
    const float* ev  = (const float*)d_in[4];
    const float* mW1 = (const float*)d_in[5];
    const float* mb1 = (const float*)d_in[6];
    const float* mW2 = (const float*)d_in[7];
    const float* mb2 = (const float*)d_in[8];
    const float* mWv = (const float*)d_in[9];
    const float* mWg = (const float*)d_in[10];
    const float* mbg = (const float*)d_in[11];
    const float* uW1 = (const float*)d_in[12];
    const float* ub1 = (const float*)d_in[13];
    const float* uW2 = (const float*)d_in[14];
    const float* ub2 = (const float*)d_in[15];
    const float* uWv = (const float*)d_in[16];
    const float* uWg = (const float*)d_in[17];
    const float* ubg = (const float*)d_in[18];
    const float* lng = (const float*)d_in[19];
    const float* lnb = (const float*)d_in[20];

    const int n = in_sizes[0] / 128;
    const int E = in_sizes[2] / 2;

    float* out_s = (float*)d_out;
    float* out_v = out_s + (size_t)n * 128;

    cudaFuncSetAttribute(edge_kernel,
                         cudaFuncAttributeMaxDynamicSharedMemorySize,
                         EDGE_SMEM_BYTES);

    zero_kernel<<<(n * 176 + 255) / 256, 256>>>(n);

    edge_kernel<<<(E + 127) / 128, 256, EDGE_SMEM_BYTES>>>(
        s, v, ei, es, ev, mW1, mb1, mW2, mb2, mWv, mWg, mbg, E);

    node_kernel<<<(n + 7) / 8, 128>>>(
        s, v, uW1, ub1, uW2, ub2, uWv, uWg, ubg, lng, lnb,
        out_s, out_v, n);
}

// round 7
// speedup vs baseline: 2.5379x; 1.2190x over previous
#include <cuda_runtime.h>
#include <cuda_bf16.h>
#include <math.h>
#include <stdint.h>

// Problem constants: N=20000, E=640000, S=128, V=16, E_DIM=32
#define MAXN 20000

__device__ float g_agg_s[MAXN * 128];
__device__ float g_agg_v[MAXN * 48];

// Pre-converted bf16 hi/lo weights (row-major [k][n]); W1 padded to 336 rows.
__device__ __nv_bfloat16 g_W1hi[336 * 128];
__device__ __nv_bfloat16 g_W1lo[336 * 128];
__device__ __nv_bfloat16 g_W2hi[128 * 128];
__device__ __nv_bfloat16 g_W2lo[128 * 128];

__device__ __forceinline__ float sigmoidf_(float x) {
    return 1.0f / (1.0f + __expf(-x));
}
__device__ __forceinline__ uint32_t smem_to_u32(const void* p) {
    uint32_t a;
    asm("{ .reg .u64 t; cvta.to.shared.u64 t, %1; cvt.u32.u64 %0, t; }"
        : "=r"(a) : "l"(p));
    return a;
}
__device__ __forceinline__ void ldsm4(uint32_t addr, uint32_t* r) {
    asm volatile("ldmatrix.sync.aligned.m8n8.x4.shared.b16 {%0,%1,%2,%3}, [%4];"
        : "=r"(r[0]), "=r"(r[1]), "=r"(r[2]), "=r"(r[3]) : "r"(addr));
}
__device__ __forceinline__ void ldsm4t(uint32_t addr, uint32_t* r) {
    asm volatile("ldmatrix.sync.aligned.m8n8.x4.trans.shared.b16 {%0,%1,%2,%3}, [%4];"
        : "=r"(r[0]), "=r"(r[1]), "=r"(r[2]), "=r"(r[3]) : "r"(addr));
}
__device__ __forceinline__ void mma_bf16(float* c, const uint32_t* a, const uint32_t* b) {
    asm volatile(
        "mma.sync.aligned.m16n8k16.row.col.f32.bf16.bf16.f32 "
        "{%0,%1,%2,%3}, {%4,%5,%6,%7}, {%8,%9}, {%0,%1,%2,%3};"
        : "+f"(c[0]), "+f"(c[1]), "+f"(c[2]), "+f"(c[3])
        : "r"(a[0]), "r"(a[1]), "r"(a[2]), "r"(a[3]), "r"(b[0]), "r"(b[1]));
}
__device__ __forceinline__ uint32_t pack_bf2(float x0, float x1) {
    __nv_bfloat162 t;
    t.x = __float2bfloat16(x0);
    t.y = __float2bfloat16(x1);
    return *(uint32_t*)&t;
}
__device__ __forceinline__ void red4(float* p, float a, float b, float c, float d) {
    asm volatile("red.global.add.v4.f32 [%0], {%1, %2, %3, %4};"
        :: "l"(p), "f"(a), "f"(b), "f"(c), "f"(d) : "memory");
}

// ---------------------------------------------------------------------------
__global__ void zero_kernel(int n) {
    int total = n * 176;
    for (int i = blockIdx.x * blockDim.x + threadIdx.x; i < total;
         i += gridDim.x * blockDim.x) {
        if (i < n * 128) g_agg_s[i] = 0.0f;
        else             g_agg_v[i - n * 128] = 0.0f;
    }
}

// One-time weight conversion to bf16 hi/lo.
__global__ void prep_weights(const float* __restrict__ W1,
                             const float* __restrict__ W2) {
    int i = blockIdx.x * blockDim.x + threadIdx.x;
    if (i < 336 * 128) {
        int k = i >> 7;
        float val = (k < 322) ? W1[i] : 0.0f;
        __nv_bfloat16 h = __float2bfloat16(val);
        g_W1hi[i] = h;
        g_W1lo[i] = __float2bfloat16(val - __bfloat162float(h));
    } else if (i < 336 * 128 + 128 * 128) {
        int j = i - 336 * 128;
        float val = W2[j];
        __nv_bfloat16 h = __float2bfloat16(val);
        g_W2hi[j] = h;
        g_W2lo[j] = __float2bfloat16(val - __bfloat162float(h));
    }
}

// ===========================================================================
// Edge kernel: 128 edges/CTA, 256 threads, mma.sync bf16 (3-term hi/lo split),
// pre-converted weights + double-buffered software-pipelined tiles.
// smem byte map (total 106624):
//   [0,69632)    T hi [128][136]bf16 @0, T lo @34816  (GEMM2 A operand)
//                during GEMM1: X tile dbl-buf @ b*12288 (hi @+0 [128]x48B, lo @+6144)
//                after GEMM2: sms f32[128][132] @0 ; then svin f32[128][100] @0
//   [69632,88064) snorm f32[128][36]   (GEMM1 only)
//                after: WgT f32[16][128] @69632 ; Wv @77824 ; sg @79936
//   [88192,105600) W tile dbl-buf: buf b @88192+b*8704 (hi 16x272B, lo @+4352)
//   [105600,106624) ssrc int[128] @105600 ; sdst @106112
// ===========================================================================
#define OB_T     0
#define OB_TLO   34816
#define OB_NORM  69632
#define OB_WGT   69632
#define OB_WV    77824
#define OB_SG    79936
#define OB_W     88192
#define OB_SRC   105600
#define OB_DST   106112
#define EDGE_SMEM_BYTES 106624
#define XBUF(b)  ((b) * 12288)
#define XLO_OFF  6144
#define WBUF(b)  (OB_W + (b) * 8704)
#define WLO_OFF  4352

__device__ __forceinline__ float fetch_x(int k, int e, int eg,
    const float* __restrict__ s, const float* __restrict__ es,
    const int* ssrc, const int* sdst, const float* snorm)
{
    if (k < 128)  return s[ssrc[e] * 128 + k];
    if (k < 256)  return s[sdst[e] * 128 + (k - 128)];
    if (k < 288)  return es[eg * 32 + (k - 256)];
    if (k == 288) return snorm[e * 36 + 32];      // edge_len = |edge_v|
    if (k < 322)  return snorm[e * 36 + (k - 289)];
    return 0.0f;                                  // K padding 322..335
}

__global__ __launch_bounds__(256, 2) void edge_kernel(
    const float* __restrict__ s, const float* __restrict__ v,
    const int* __restrict__ ei, const float* __restrict__ es,
    const float* __restrict__ ev,
    const float* __restrict__ b1, const float* __restrict__ b2,
    const float* __restrict__ Wv, const float* __restrict__ Wg,
    const float* __restrict__ bg, int E)
{
    extern __shared__ __align__(16) char smraw[];
    float* smf = (float*)smraw;
    const uint32_t smb = smem_to_u32(smraw);

    const int tid = threadIdx.x;
    const int lane = tid & 31;
    const int wid = tid >> 5;
    const int e0 = blockIdx.x * 128;
    const int nval = min(128, E - e0);

    int* ssrc = (int*)(smraw + OB_SRC);
    int* sdst = (int*)(smraw + OB_DST);
    float* snorm = (float*)(smraw + OB_NORM);

    // ---- phase 1: indices + vector norms ----
    if (tid < 128) {
        int ee = e0 + min(tid, nval - 1);
        ssrc[tid] = ei[ee];
        sdst[tid] = ei[E + ee];
    }
    __syncthreads();
    for (int q = tid; q < 128 * 33; q += 256) {
        int e = q / 33, j = q - e * 33;
        int eg = e0 + min(e, nval - 1);
        float a, b, c;
        if (j < 16) {
            const float* p = v + (size_t)ssrc[e] * 48 + j * 3;
            a = p[0]; b = p[1]; c = p[2];
        } else if (j < 32) {
            const float* p = v + (size_t)sdst[e] * 48 + (j - 16) * 3;
            a = p[0]; b = p[1]; c = p[2];
        } else {
            const float* p = ev + (size_t)eg * 3;
            a = p[0]; b = p[1]; c = p[2];
        }
        snorm[e * 36 + j] = sqrtf(fmaxf(a * a + b * b + c * c, 1e-8f));
    }
    __syncthreads();

    // warp tiling: 4 warps along M (edges), 2 along N
    const int mw = (wid & 3) * 32;
    const int nw = (wid >> 2) * 64;
    const int arow = lane & 15;
    const int acol = lane >> 4;

    // per-thread tile-build coordinates
    const int xe_base = tid >> 3;          // e for item0 (items step e by 32)
    const int xk2 = (tid & 7) * 2;         // k pair within tile
    const int wkk = tid >> 4;              // W tile row
    const int wn8 = (tid & 15) * 8;        // W tile col group

    float acc[2][8][4];
#pragma unroll
    for (int mt = 0; mt < 2; ++mt)
#pragma unroll
        for (int nt = 0; nt < 8; ++nt)
#pragma unroll
            for (int r = 0; r < 4; ++r) acc[mt][nt][r] = 0.0f;

    float xr[4][2];
    uint4 wh, wl;

    // ---- prologue: tile 0 ----
    {
#pragma unroll
        for (int it = 0; it < 4; ++it) {
            int e = xe_base + it * 32;
            int eg = e0 + min(e, nval - 1);
            xr[it][0] = fetch_x(xk2,     e, eg, s, es, ssrc, sdst, snorm);
            xr[it][1] = fetch_x(xk2 + 1, e, eg, s, es, ssrc, sdst, snorm);
        }
        wh = *(const uint4*)&g_W1hi[wkk * 128 + wn8];
        wl = *(const uint4*)&g_W1lo[wkk * 128 + wn8];
#pragma unroll
        for (int it = 0; it < 4; ++it) {
            int e = xe_base + it * 32;
            uint32_t ph = pack_bf2(xr[it][0], xr[it][1]);
            __nv_bfloat162 u = *(__nv_bfloat162*)&ph;
            uint32_t pl = pack_bf2(xr[it][0] - __bfloat162float(u.x),
                                   xr[it][1] - __bfloat162float(u.y));
            *(uint32_t*)(smraw + XBUF(0) + e * 48 + xk2 * 2) = ph;
            *(uint32_t*)(smraw + XBUF(0) + XLO_OFF + e * 48 + xk2 * 2) = pl;
        }
        *(uint4*)(smraw + WBUF(0) + wkk * 272 + wn8 * 2) = wh;
        *(uint4*)(smraw + WBUF(0) + WLO_OFF + wkk * 272 + wn8 * 2) = wl;
    }
    __syncthreads();

    // ================= GEMM1: h = X @ W1  (K=336, 21 tiles) ==================
    for (int kt = 0; kt < 21; ++kt) {
        const int cur = kt & 1, nxt = cur ^ 1;
        const bool more = (kt + 1 < 21);
        if (more) {
            int kbase = (kt + 1) * 16;
#pragma unroll
            for (int it = 0; it < 4; ++it) {
                int e = xe_base + it * 32;
                int eg = e0 + min(e, nval - 1);
                xr[it][0] = fetch_x(kbase + xk2,     e, eg, s, es, ssrc, sdst, snorm);
                xr[it][1] = fetch_x(kbase + xk2 + 1, e, eg, s, es, ssrc, sdst, snorm);
            }
            wh = *(const uint4*)&g_W1hi[(kbase + wkk) * 128 + wn8];
            wl = *(const uint4*)&g_W1lo[(kbase + wkk) * 128 + wn8];
        }

        // mma on current buffer
        {
            uint32_t ah[2][4], al[2][4];
#pragma unroll
            for (int mt = 0; mt < 2; ++mt) {
                uint32_t aaddr = smb + XBUF(cur) + (mw + 16 * mt + arow) * 48 + acol * 16;
                ldsm4(aaddr, ah[mt]);
                ldsm4(aaddr + XLO_OFF, al[mt]);
            }
#pragma unroll
            for (int nb = 0; nb < 4; ++nb) {
                uint32_t bh[4], bl[4];
                uint32_t baddr = smb + WBUF(cur) + arow * 272 + (nw + nb * 16 + acol * 8) * 2;
                ldsm4t(baddr, bh);
                ldsm4t(baddr + WLO_OFF, bl);
#pragma unroll
                for (int mt = 0; mt < 2; ++mt) {
                    mma_bf16(acc[mt][2 * nb],     ah[mt], bh);
                    mma_bf16(acc[mt][2 * nb + 1], ah[mt], bh + 2);
                    mma_bf16(acc[mt][2 * nb],     al[mt], bh);
                    mma_bf16(acc[mt][2 * nb + 1], al[mt], bh + 2);
                    mma_bf16(acc[mt][2 * nb],     ah[mt], bl);
                    mma_bf16(acc[mt][2 * nb + 1], ah[mt], bl + 2);
                }
            }
        }

        if (more) {
#pragma unroll
            for (int it = 0; it < 4; ++it) {
                int e = xe_base + it * 32;
                uint32_t ph = pack_bf2(xr[it][0], xr[it][1]);
                __nv_bfloat162 u = *(__nv_bfloat162*)&ph;
                uint32_t pl = pack_bf2(xr[it][0] - __bfloat162float(u.x),
                                       xr[it][1] - __bfloat162float(u.y));
                *(uint32_t*)(smraw + XBUF(nxt) + e * 48 + xk2 * 2) = ph;
                *(uint32_t*)(smraw + XBUF(nxt) + XLO_OFF + e * 48 + xk2 * 2) = pl;
            }
            *(uint4*)(smraw + WBUF(nxt) + wkk * 272 + wn8 * 2) = wh;
            *(uint4*)(smraw + WBUF(nxt) + WLO_OFF + wkk * 272 + wn8 * 2) = wl;
        }
        __syncthreads();
    }

    // ---- epilogue 1: +b1, silu, bf16 split -> T (X bufs dead) ----
#pragma unroll
    for (int mt = 0; mt < 2; ++mt) {
        int r0 = mw + 16 * mt + (lane >> 2);
#pragma unroll
        for (int nt = 0; nt < 8; ++nt) {
            int n = nw + nt * 8 + (lane & 3) * 2;
            float2 bb = *(const float2*)&b1[n];
            float h0 = acc[mt][nt][0] + bb.x, h1 = acc[mt][nt][1] + bb.y;
            float h2 = acc[mt][nt][2] + bb.x, h3 = acc[mt][nt][3] + bb.y;
            float t0 = h0 * sigmoidf_(h0), t1 = h1 * sigmoidf_(h1);
            float t2 = h2 * sigmoidf_(h2), t3 = h3 * sigmoidf_(h3);
            uint32_t p0h = pack_bf2(t0, t1);
            __nv_bfloat162 u0 = *(__nv_bfloat162*)&p0h;
            uint32_t p0l = pack_bf2(t0 - __bfloat162float(u0.x), t1 - __bfloat162float(u0.y));
            uint32_t p1h = pack_bf2(t2, t3);
            __nv_bfloat162 u1 = *(__nv_bfloat162*)&p1h;
            uint32_t p1l = pack_bf2(t2 - __bfloat162float(u1.x), t3 - __bfloat162float(u1.y));
            *(uint32_t*)(smraw + OB_T   + r0 * 272 + n * 2) = p0h;
            *(uint32_t*)(smraw + OB_TLO + r0 * 272 + n * 2) = p0l;
            *(uint32_t*)(smraw + OB_T   + (r0 + 8) * 272 + n * 2) = p1h;
            *(uint32_t*)(smraw + OB_TLO + (r0 + 8) * 272 + n * 2) = p1l;
        }
    }
    __syncthreads();

    // stage Wg^T and Wv (norm region dead)
    for (int q = tid; q < 2048; q += 256) {
        int w = q >> 7, c = q & 127;
        smf[OB_WGT / 4 + q] = Wg[c * 16 + w];
    }
    for (int q = tid; q < 528; q += 256) smf[OB_WV / 4 + q] = Wv[q];

    // ================= GEMM2: m_s = silu(h) @ W2  (K=128, 8 tiles) ===========
#pragma unroll
    for (int mt = 0; mt < 2; ++mt)
#pragma unroll
        for (int nt = 0; nt < 8; ++nt)
#pragma unroll
            for (int r = 0; r < 4; ++r) acc[mt][nt][r] = 0.0f;

    wh = *(const uint4*)&g_W2hi[wkk * 128 + wn8];
    wl = *(const uint4*)&g_W2lo[wkk * 128 + wn8];
    *(uint4*)(smraw + WBUF(0) + wkk * 272 + wn8 * 2) = wh;
    *(uint4*)(smraw + WBUF(0) + WLO_OFF + wkk * 272 + wn8 * 2) = wl;
    __syncthreads();

    for (int kt = 0; kt < 8; ++kt) {
        const int cur = kt & 1, nxt = cur ^ 1;
        const bool more = (kt + 1 < 8);
        if (more) {
            wh = *(const uint4*)&g_W2hi[((kt + 1) * 16 + wkk) * 128 + wn8];
            wl = *(const uint4*)&g_W2lo[((kt + 1) * 16 + wkk) * 128 + wn8];
        }
        {
            uint32_t ah[2][4], al[2][4];
#pragma unroll
            for (int mt = 0; mt < 2; ++mt) {
                uint32_t aaddr = smb + OB_T + (mw + 16 * mt + arow) * 272
                               + (kt * 16 + acol * 8) * 2;
                ldsm4(aaddr, ah[mt]);
                ldsm4(aaddr + (OB_TLO - OB_T), al[mt]);
            }
#pragma unroll
            for (int nb = 0; nb < 4; ++nb) {
                uint32_t bh[4], bl[4];
                uint32_t baddr = smb + WBUF(cur) + arow * 272 + (nw + nb * 16 + acol * 8) * 2;
                ldsm4t(baddr, bh);
                ldsm4t(baddr + WLO_OFF, bl);
#pragma unroll
                for (int mt = 0; mt < 2; ++mt) {
                    mma_bf16(acc[mt][2 * nb],     ah[mt], bh);
                    mma_bf16(acc[mt][2 * nb + 1], ah[mt], bh + 2);
                    mma_bf16(acc[mt][2 * nb],     al[mt], bh);
                    mma_bf16(acc[mt][2 * nb + 1], al[mt], bh + 2);
                    mma_bf16(acc[mt][2 * nb],     ah[mt], bl);
                    mma_bf16(acc[mt][2 * nb + 1], ah[mt], bl + 2);
                }
            }
        }
        if (more) {
            *(uint4*)(smraw + WBUF(nxt) + wkk * 272 + wn8 * 2) = wh;
            *(uint4*)(smraw + WBUF(nxt) + WLO_OFF + wkk * 272 + wn8 * 2) = wl;
        }
        __syncthreads();
    }

    // ---- epilogue 2: +b2 -> sms (aliases T; all T reads complete) ----
    float* sms = smf;  // [128][132]
#pragma unroll
    for (int mt = 0; mt < 2; ++mt) {
        int r0 = mw + 16 * mt + (lane >> 2);
#pragma unroll
        for (int nt = 0; nt < 8; ++nt) {
            int n = nw + nt * 8 + (lane & 3) * 2;
            float2 bb = *(const float2*)&b2[n];
            sms[r0 * 132 + n]       = acc[mt][nt][0] + bb.x;
            sms[r0 * 132 + n + 1]   = acc[mt][nt][1] + bb.y;
            sms[(r0 + 8) * 132 + n]     = acc[mt][nt][2] + bb.x;
            sms[(r0 + 8) * 132 + n + 1] = acc[mt][nt][3] + bb.y;
        }
    }
    __syncthreads();

    // ---- gates: sigmoid(ms @ Wg + bg) ----
    float* sg = smf + OB_SG / 4;
    for (int q = tid; q < 2048; q += 256) {
        int e = q >> 4, w = q & 15;
        float g = 0.0f;
        const float4* ms4 = (const float4*)(sms + e * 132);
        const float4* wg4 = (const float4*)(smf + OB_WGT / 4 + w * 128);
#pragma unroll 8
        for (int c4 = 0; c4 < 32; ++c4) {
            float4 a = ms4[c4], b = wg4[c4];
            g += a.x * b.x + a.y * b.y + a.z * b.z + a.w * b.w;
        }
        sg[e * 16 + w] = sigmoidf_(g + bg[w]);
    }
    __syncthreads();

    // ---- scatter-add m_s ----
    for (int q = tid; q < 4096; q += 256) {
        int e = q >> 5, cq = q & 31;
        if (e < nval) {
            const float* p = sms + e * 132 + cq * 4;
            red4(&g_agg_s[(size_t)sdst[e] * 128 + cq * 4], p[0], p[1], p[2], p[3]);
        }
    }
    __syncthreads();

    // ---- gather vin (aliases sms, dead) ----
    float* svin = smf;  // [128][100]
    for (int q = tid; q < 128 * 99; q += 256) {
        int e = q / 99, j = q - e * 99;
        int eg = e0 + min(e, nval - 1);
        float val;
        if (j < 48)      val = v[(size_t)ssrc[e] * 48 + j];
        else if (j < 96) val = v[(size_t)sdst[e] * 48 + (j - 48)];
        else             val = ev[(size_t)eg * 3 + (j - 96)];
        svin[e * 100 + j] = val;
    }
    __syncthreads();

    // ---- v projection * gate, scatter-add ----
    for (int q = tid; q < 1536; q += 256) {
        int e = q / 12, rq = q - e * 12;
        if (e >= nval) continue;
        float out[4];
#pragma unroll
        for (int u = 0; u < 4; ++u) {
            int r = rq * 4 + u, w = r / 3, c3 = r - w * 3;
            float a = 0.0f;
#pragma unroll
            for (int j = 0; j < 33; ++j)
                a = fmaf(svin[e * 100 + j * 3 + c3], smf[OB_WV / 4 + j * 16 + w], a);
            out[u] = a * sg[e * 16 + w];
        }
        red4(&g_agg_v[(size_t)sdst[e] * 48 + rq * 4], out[0], out[1], out[2], out[3]);
    }
}

// ---------------------------------------------------------------------------
// Node update kernel (r1, verified correct)
// ---------------------------------------------------------------------------
__global__ __launch_bounds__(128) void node_kernel(
    const float* __restrict__ s, const float* __restrict__ v,
    const float* __restrict__ W1, const float* __restrict__ b1,
    const float* __restrict__ W2, const float* __restrict__ b2,
    const float* __restrict__ Wv, const float* __restrict__ Wg,
    const float* __restrict__ bg, const float* __restrict__ lng,
    const float* __restrict__ lnb,
    float* __restrict__ out_s, float* __restrict__ out_v, int n)
{
    __shared__ float xu[8][292];
    __shared__ float vin[8][96];
    __shared__ float tt[8][128];
    __shared__ float dsm[8][132];
    __shared__ float gate[8][16];
    __shared__ float rsum[8][4], rsq[8][4];

    const int tid = threadIdx.x;
    const int n0 = blockIdx.x * 8;

    for (int idx = tid; idx < 8 * 256; idx += 128) {
        int i = idx >> 8, k = idx & 255;
        int nd = min(n0 + i, n - 1);
        xu[i][k] = (k < 128) ? s[nd * 128 + k] : g_agg_s[nd * 128 + (k - 128)];
    }
    for (int idx = tid; idx < 8 * 96; idx += 128) {
        int i = idx / 96, k = idx - i * 96;
        int nd = min(n0 + i, n - 1);
        vin[i][k] = (k < 48) ? v[nd * 48 + k] : g_agg_v[nd * 48 + (k - 48)];
    }
    __syncthreads();
    for (int idx = tid; idx < 8 * 32; idx += 128) {
        int i = idx >> 5, j = idx & 31;
        float a = vin[i][j * 3], b = vin[i][j * 3 + 1], c = vin[i][j * 3 + 2];
        xu[i][256 + j] = sqrtf(fmaxf(a * a + b * b + c * c, 1e-8f));
    }
    __syncthreads();

    const int c = tid;
    float acc[8];
    {
        float bb = b1[c];
#pragma unroll
        for (int i = 0; i < 8; ++i) acc[i] = bb;
    }
    for (int k = 0; k < 288; ++k) {
        float w = W1[k * 128 + c];
#pragma unroll
        for (int i = 0; i < 8; ++i) acc[i] = fmaf(xu[i][k], w, acc[i]);
    }
#pragma unroll
    for (int i = 0; i < 8; ++i) {
        float h = acc[i];
        tt[i][c] = h * sigmoidf_(h);
    }
    __syncthreads();

    float acc2[8];
    {
        float bb = b2[c];
#pragma unroll
        for (int i = 0; i < 8; ++i) acc2[i] = bb;
    }
    for (int k = 0; k < 128; ++k) {
        float w = W2[k * 128 + c];
#pragma unroll
        for (int i = 0; i < 8; ++i) acc2[i] = fmaf(tt[i][k], w, acc2[i]);
    }
#pragma unroll
    for (int i = 0; i < 8; ++i) dsm[i][c] = acc2[i];
    __syncthreads();

    {
        int i = tid >> 4, w = tid & 15;
        float g = bg[w];
        for (int cc = 0; cc < 128; ++cc)
            g = fmaf(dsm[i][cc], Wg[cc * 16 + w], g);
        gate[i][w] = sigmoidf_(g);
    }

    float val[8];
#pragma unroll
    for (int i = 0; i < 8; ++i) {
        int nd = min(n0 + i, n - 1);
        val[i] = s[nd * 128 + c] + acc2[i];
    }
    const int lane = tid & 31, wq = tid >> 5;
    float psum[8], psq[8];
#pragma unroll
    for (int i = 0; i < 8; ++i) { psum[i] = val[i]; psq[i] = val[i] * val[i]; }
#pragma unroll
    for (int off = 16; off > 0; off >>= 1) {
#pragma unroll
        for (int i = 0; i < 8; ++i) {
            psum[i] += __shfl_xor_sync(0xffffffffu, psum[i], off);
            psq[i]  += __shfl_xor_sync(0xffffffffu, psq[i],  off);
        }
    }
    if (lane == 0) {
#pragma unroll
        for (int i = 0; i < 8; ++i) { rsum[i][wq] = psum[i]; rsq[i][wq] = psq[i]; }
    }
    __syncthreads();

#pragma unroll
    for (int i = 0; i < 8; ++i) {
        if (n0 + i >= n) continue;
        float sum = rsum[i][0] + rsum[i][1] + rsum[i][2] + rsum[i][3];
        float sq  = rsq[i][0] + rsq[i][1] + rsq[i][2] + rsq[i][3];
        float mu  = sum * (1.0f / 128.0f);
        float var = sq * (1.0f / 128.0f) - mu * mu;
        float o = (val[i] - mu) * rsqrtf(var + 1e-5f) * lng[c] + lnb[c];
        out_s[(n0 + i) * 128 + c] = o;
    }

    for (int q = tid; q < 8 * 48; q += 128) {
        int i = q / 48, r = q - i * 48;
        if (n0 + i >= n) continue;
        int w = r / 3, cc = r - w * 3;
        float a = 0.0f;
#pragma unroll
        for (int j = 0; j < 32; ++j)
            a = fmaf(vin[i][j * 3 + cc], Wv[j * 16 + w], a);
        a *= gate[i][w];
        out_v[(n0 + i) * 48 + r] = v[(n0 + i) * 48 + r] + a;
    }
}

// ---------------------------------------------------------------------------
extern "C" void kernel_launch(void* const* d_in, const int* in_sizes, int n_in,
                              void* d_out, int out_size)
{
    const float* s   = (const float*)d_in[0];
    const float* v   = (const float*)d_in[1];
    const int*   ei  = (const int*)  d_in[2];
    const float* es  = (const float*)d_in[3];
    const float* ev  = (const float*)d_in[4];
    const float* mW1 = (const float*)d_in[5];
    const float* mb1 = (const float*)d_in[6];
    const float* mW2 = (const float*)d_in[7];
    const float* mb2 = (const float*)d_in[8];
    const float* mWv = (const float*)d_in[9];
    const float* mWg = (const float*)d_in[10];
    const float* mbg = (const float*)d_in[11];
    const float* uW1 = (const float*)d_in[12];
    const float* ub1 = (const float*)d_in[13];
    const float* uW2 = (const float*)d_in[14];
    const float* ub2 = (const float*)d_in[15];
    const float* uWv = (const float*)d_in[16];
    const float* uWg = (const float*)d_in[17];
    const float* ubg = (const float*)d_in[18];
    const float* lng = (const float*)d_in[19];
    const float* lnb = (const float*)d_in[20];

    const int n = in_sizes[0] / 128;
    const int E = in_sizes[2] / 2;

    float* out_s = (float*)d_out;
    float* out_v = out_s + (size_t)n * 128;

    cudaFuncSetAttribute(edge_kernel,
                         cudaFuncAttributeMaxDynamicSharedMemorySize,
                         EDGE_SMEM_BYTES);

    zero_kernel<<<(n * 176 + 255) / 256, 256>>>(n);
    prep_weights<<<(336 * 128 + 128 * 128 + 255) / 256, 256>>>(mW1, mW2);

    edge_kernel<<<(E + 127) / 128, 256, EDGE_SMEM_BYTES>>>(
        s, v, ei, es, ev, mb1, mb2, mWv, mWg, mbg, E);

    node_kernel<<<(n + 7) / 8, 128>>>(
        s, v, uW1, ub1, uW2, ub2, uWv, uWg, ubg, lng, lnb,
        out_s, out_v, n);
}